// round 1
// baseline (speedup 1.0000x reference)
#include <cuda_runtime.h>
#include <cstdint>

#define N_CODES 100000
#define CODE_DIM 256
#define HIDDEN 128
#define HEADS 4
#define N_SPEC 256

#define NBA 592   // score-pass blocks (256 thr = 8 warps each)
#define NBB 296   // weighted-pass blocks
#define L2E 1.4426950408889634f

// ---------------- scratch (device globals; no allocation allowed) ----------
__device__ __align__(16) float g_v[HEADS * CODE_DIM];      // v[h][d] = W[h]@a2[h]
__device__ float g_c[HEADS];                                // score constants
__device__ __align__(16) float g_e[N_CODES * HEADS];        // leaky scores (1.6MB)
__device__ float g_partA[NBA * 8];                          // per-block (m,s) per head
__device__ float g_MZ[8];                                   // M[4], Z[4]
__device__ __align__(16) float g_partB[NBB * HEADS * CODE_DIM];
__device__ __align__(16) float g_mho[HEADS * HIDDEN];       // multi-head output

// ---------------- K1: prep -------------------------------------------------
// blocks 0..7  : v[h][d] = sum_k W[h,d,k]*a2[h,k]   (1024 dot products, len 128)
// blocks 8..11 : c[h] = (p@W[h]+b[h])·a1[h] + b[h]·a2[h]
__global__ void k_prep(const float* __restrict__ W, const float* __restrict__ a,
                       const float* __restrict__ p, const float* __restrict__ bb) {
    if (blockIdx.x < 8) {
        int idx = blockIdx.x * 128 + threadIdx.x;       // 0..1023
        int h = idx >> 8, d = idx & 255;
        const float4* wr = (const float4*)(W + (size_t)(h * 256 + d) * 128);
        const float4* a2 = (const float4*)(a + h * 256 + 128);
        float acc = 0.f;
        #pragma unroll
        for (int q = 0; q < 32; q++) {
            float4 w = wr[q], x = a2[q];
            acc += w.x * x.x + w.y * x.y + w.z * x.z + w.w * x.w;
        }
        g_v[idx] = acc;
    } else {
        int h = blockIdx.x - 8;
        int k = threadIdx.x;                            // 0..127
        float ph = bb[h * 128 + k];
        const float* wp = W + (size_t)h * 256 * 128 + k;
        for (int d = 0; d < 256; d++) ph = fmaf(p[d], wp[(size_t)d * 128], ph);
        float val = ph * a[h * 256 + k] + bb[h * 128 + k] * a[h * 256 + 128 + k];
        __shared__ float red[128];
        red[k] = val;
        __syncthreads();
        for (int o = 64; o; o >>= 1) {
            if (k < o) red[k] += red[k + o];
            __syncthreads();
        }
        if (k == 0) g_c[h] = red[0];
    }
}

// ---------------- K2: scores (pass A) --------------------------------------
// warp-per-code: e[h,n] = leaky(c[h] + code[n]·v[h]); online softmax partials.
__global__ void k_scores(const float* __restrict__ code) {
    int wid = threadIdx.x >> 5, lane = threadIdx.x & 31;
    int gwarp = blockIdx.x * 8 + wid;
    const int nwarps = NBA * 8;

    // v held in registers: lane owns elements [lane*8, lane*8+8) for each head
    float vr[4][8];
    #pragma unroll
    for (int h = 0; h < 4; h++) {
        const float4* vp = (const float4*)(g_v + h * 256 + lane * 8);
        float4 v0 = vp[0], v1 = vp[1];
        vr[h][0] = v0.x; vr[h][1] = v0.y; vr[h][2] = v0.z; vr[h][3] = v0.w;
        vr[h][4] = v1.x; vr[h][5] = v1.y; vr[h][6] = v1.z; vr[h][7] = v1.w;
    }
    float c0 = g_c[0], c1 = g_c[1], c2 = g_c[2], c3 = g_c[3];

    float m[4], s[4];
    #pragma unroll
    for (int h = 0; h < 4; h++) { m[h] = -1e30f; s[h] = 0.f; }

    for (int n = gwarp; n < N_CODES; n += nwarps) {
        const float4* cp = (const float4*)(code + (size_t)n * 256 + lane * 8);
        float4 x0 = cp[0], x1 = cp[1];
        float e[4];
        #pragma unroll
        for (int h = 0; h < 4; h++) {
            e[h] = vr[h][0] * x0.x + vr[h][1] * x0.y + vr[h][2] * x0.z + vr[h][3] * x0.w
                 + vr[h][4] * x1.x + vr[h][5] * x1.y + vr[h][6] * x1.z + vr[h][7] * x1.w;
        }
        #pragma unroll
        for (int o = 16; o; o >>= 1) {
            #pragma unroll
            for (int h = 0; h < 4; h++) e[h] += __shfl_xor_sync(0xffffffffu, e[h], o);
        }
        e[0] += c0; e[1] += c1; e[2] += c2; e[3] += c3;
        #pragma unroll
        for (int h = 0; h < 4; h++) e[h] = e[h] >= 0.f ? e[h] : 0.2f * e[h];
        if (lane == 0)
            *((float4*)(g_e + (size_t)n * 4)) = make_float4(e[0], e[1], e[2], e[3]);
        #pragma unroll
        for (int h = 0; h < 4; h++) {
            float mn = fmaxf(m[h], e[h]);
            s[h] = s[h] * exp2f((m[h] - mn) * L2E) + exp2f((e[h] - mn) * L2E);
            m[h] = mn;
        }
    }

    __shared__ float shm[8][4], shs[8][4];
    if (lane == 0) {
        #pragma unroll
        for (int h = 0; h < 4; h++) { shm[wid][h] = m[h]; shs[wid][h] = s[h]; }
    }
    __syncthreads();
    if (threadIdx.x < 4) {
        int h = threadIdx.x;
        float M = -1e30f;
        for (int w = 0; w < 8; w++) M = fmaxf(M, shm[w][h]);
        float S = 0.f;
        for (int w = 0; w < 8; w++)
            if (shs[w][h] > 0.f) S += shs[w][h] * exp2f((shm[w][h] - M) * L2E);
        g_partA[blockIdx.x * 8 + h * 2]     = M;
        g_partA[blockIdx.x * 8 + h * 2 + 1] = S;
    }
}

// ---------------- K3: global softmax max/sum combine ------------------------
__global__ void k_mzred() {
    int wid = threadIdx.x >> 5, lane = threadIdx.x & 31;
    if (wid >= 4) return;
    int h = wid;
    float M = -1e30f;
    for (int b = lane; b < NBA; b += 32) M = fmaxf(M, g_partA[b * 8 + h * 2]);
    #pragma unroll
    for (int o = 16; o; o >>= 1) M = fmaxf(M, __shfl_xor_sync(0xffffffffu, M, o));
    float S = 0.f;
    for (int b = lane; b < NBA; b += 32) {
        float mb = g_partA[b * 8 + h * 2];
        float sb = g_partA[b * 8 + h * 2 + 1];
        if (sb > 0.f) S += sb * exp2f((mb - M) * L2E);
    }
    #pragma unroll
    for (int o = 16; o; o >>= 1) S += __shfl_xor_sync(0xffffffffu, S, o);
    if (lane == 0) { g_MZ[h] = M; g_MZ[4 + h] = S; }
}

// ---------------- K4: weighted sum (pass B) ---------------------------------
// s[h][d] = sum_n alpha[h,n]*code[n][d]; alpha already normalized (1/Z folded).
// tile 64 codes: stage w (64x4) in shared, thread t owns dim d=t.
__global__ void k_weighted(const float* __restrict__ code) {
    __shared__ float4 w_sh[64];
    __shared__ float Msh[4], invZ[4];
    int t = threadIdx.x;
    if (t < 4) { Msh[t] = g_MZ[t]; invZ[t] = 1.0f / g_MZ[4 + t]; }
    __syncthreads();

    float a0 = 0.f, a1 = 0.f, a2 = 0.f, a3 = 0.f;
    const int ntiles = (N_CODES + 63) >> 6;
    int si = t >> 2, sh = t & 3;
    float Mh = Msh[sh], iZ = invZ[sh];

    for (int tile = blockIdx.x; tile < ntiles; tile += NBB) {
        int n0 = tile << 6;
        __syncthreads();   // previous tile's w_sh reads done
        {
            int n = n0 + si;
            float w = 0.f;
            if (n < N_CODES) w = exp2f((g_e[n * 4 + sh] - Mh) * L2E) * iZ;
            ((float*)w_sh)[t] = w;
        }
        __syncthreads();
        int lim = min(64, N_CODES - n0);
        const float* cp = code + (size_t)n0 * 256 + t;
        for (int j = 0; j < lim; j++) {
            float4 w4 = w_sh[j];
            float x = cp[(size_t)j * 256];
            a0 = fmaf(w4.x, x, a0);
            a1 = fmaf(w4.y, x, a1);
            a2 = fmaf(w4.z, x, a2);
            a3 = fmaf(w4.w, x, a3);
        }
    }
    g_partB[(blockIdx.x * 4 + 0) * 256 + t] = a0;
    g_partB[(blockIdx.x * 4 + 1) * 256 + t] = a1;
    g_partB[(blockIdx.x * 4 + 2) * 256 + t] = a2;
    g_partB[(blockIdx.x * 4 + 3) * 256 + t] = a3;
}

// ---------------- K5: reduce partials + agg projection ----------------------
// block h: s[h][d] = sum_b partB; mho[h*128+k] = s[h]@W[h][:,k] + b[h,k]
__global__ void k_agg(const float* __restrict__ W, const float* __restrict__ bb,
                      float* __restrict__ out) {
    int h = blockIdx.x, t = threadIdx.x;
    __shared__ float s_sh[256];
    for (int d = t; d < 256; d += 128) {
        float acc = 0.f;
        for (int b2 = 0; b2 < NBB; b2++) acc += g_partB[(b2 * 4 + h) * 256 + d];
        s_sh[d] = acc;
    }
    __syncthreads();
    float acc = bb[h * 128 + t];
    const float* wp = W + (size_t)h * 256 * 128 + t;
    #pragma unroll 8
    for (int d = 0; d < 256; d++) acc = fmaf(s_sh[d], wp[(size_t)d * 128], acc);
    g_mho[h * 128 + t] = acc;
    out[256 + h * 128 + t] = acc;     // multi_head_output after logits
}

// ---------------- K6: specialty logits --------------------------------------
// warp-per-output: logits[j] = mho @ Wc[j] + bc[j]
__global__ void k_logits(const float* __restrict__ Wc, const float* __restrict__ bc,
                         float* __restrict__ out) {
    int wid = threadIdx.x >> 5, lane = threadIdx.x & 31;
    int j = blockIdx.x * 4 + wid;
    const float4* wp = (const float4*)(Wc + (size_t)j * 512);
    const float4* mp = (const float4*)g_mho;
    float acc = 0.f;
    #pragma unroll 4
    for (int q = lane; q < 128; q += 32) {
        float4 w = wp[q], m = mp[q];
        acc += w.x * m.x + w.y * m.y + w.z * m.z + w.w * m.w;
    }
    #pragma unroll
    for (int o = 16; o; o >>= 1) acc += __shfl_xor_sync(0xffffffffu, acc, o);
    if (lane == 0) out[j] = acc + bc[j];
}

// ---------------- launch -----------------------------------------------------
extern "C" void kernel_launch(void* const* d_in, const int* in_sizes, int n_in,
                              void* d_out, int out_size) {
    const float* p    = (const float*)d_in[0];  // provider_emb (256)
    const float* code = (const float*)d_in[1];  // code_embs (100000x256)
    const float* W    = (const float*)d_in[2];  // (4x256x128)
    const float* bb   = (const float*)d_in[3];  // (4x128)
    const float* a    = (const float*)d_in[4];  // (4x256)
    const float* Wc   = (const float*)d_in[5];  // (256x512)
    const float* bc   = (const float*)d_in[6];  // (256)
    float* out = (float*)d_out;                 // [logits(256), mho(512)]

    k_prep    <<<12,  128>>>(W, a, p, bb);
    k_scores  <<<NBA, 256>>>(code);
    k_mzred   <<<1,   128>>>();
    k_weighted<<<NBB, 256>>>(code);
    k_agg     <<<4,   128>>>(W, bb, out);
    k_logits  <<<64,  128>>>(Wc, bc, out);
}

// round 2
// speedup vs baseline: 1.1981x; 1.1981x over previous
#include <cuda_runtime.h>
#include <cstdint>

#define N_CODES 100000
#define CODE_DIM 256
#define HIDDEN 128
#define HEADS 4
#define N_SPEC 256

#define ROWS 16                 // codes per tile
#define NT (N_CODES / ROWS)     // 6250 tiles (exact)
#define GRID 592                // 4 blocks per SM on 148 SMs
#define L2E 1.4426950408889634f

// ---------------- scratch (device globals) ----------------------------------
__device__ __align__(16) float g_v[HEADS * CODE_DIM];   // v[h][d] = W[h]@a2[h]
__device__ float g_c[HEADS];                            // score constants
__device__ __align__(16) float g_partB[GRID * HEADS * CODE_DIM]; // block partial sums
__device__ float g_mb[GRID * HEADS];                    // block max
__device__ float g_zb[GRID * HEADS];                    // block Z partial
__device__ __align__(16) float g_mho[HEADS * HIDDEN];

// ---------------- K1: prep ---------------------------------------------------
__global__ void k_prep(const float* __restrict__ W, const float* __restrict__ a,
                       const float* __restrict__ p, const float* __restrict__ bb) {
    if (blockIdx.x < 8) {
        int idx = blockIdx.x * 128 + threadIdx.x;   // 0..1023
        int h = idx >> 8, d = idx & 255;
        const float4* wr = (const float4*)(W + (size_t)(h * 256 + d) * 128);
        const float4* a2 = (const float4*)(a + h * 256 + 128);
        float acc = 0.f;
        #pragma unroll
        for (int q = 0; q < 32; q++) {
            float4 w = wr[q], x = a2[q];
            acc += w.x * x.x + w.y * x.y + w.z * x.z + w.w * x.w;
        }
        g_v[idx] = acc;
    } else {
        int h = blockIdx.x - 8;
        int k = threadIdx.x;                        // 0..127
        float ph = bb[h * 128 + k];
        const float* wp = W + (size_t)h * 256 * 128 + k;
        for (int d = 0; d < 256; d++) ph = fmaf(p[d], wp[(size_t)d * 128], ph);
        float val = ph * a[h * 256 + k] + bb[h * 128 + k] * a[h * 256 + 128 + k];
        __shared__ float red[128];
        red[k] = val;
        __syncthreads();
        for (int o = 64; o; o >>= 1) {
            if (k < o) red[k] += red[k + o];
            __syncthreads();
        }
        if (k == 0) g_c[h] = red[0];
    }
}

// ---------------- cp.async helpers ------------------------------------------
__device__ __forceinline__ void cp_async16(void* smem, const void* gmem) {
    uint32_t s = (uint32_t)__cvta_generic_to_shared(smem);
    asm volatile("cp.async.cg.shared.global [%0], [%1], 16;\n" :: "r"(s), "l"(gmem));
}
__device__ __forceinline__ void cp_commit() {
    asm volatile("cp.async.commit_group;\n" ::: "memory");
}
__device__ __forceinline__ void cp_wait1() {
    asm volatile("cp.async.wait_group 1;\n" ::: "memory");
}

// ---------------- K2: fused single-pass scores + weighted sum ----------------
// Per tile of 16 codes (staged in shared, double-buffered):
//   stage C: warp-per-2-codes dot products -> e (leaky applied)
//   stage M: warp 0 updates block online-softmax max, computes weights + Z
//   stage G: all 256 threads (thread t owns dim t) accumulate weighted sum
__global__ void __launch_bounds__(256, 4) k_fused(const float* __restrict__ code) {
    __shared__ float buf[2][ROWS * 256];
    __shared__ float e_sh[64];      // [h][16]
    __shared__ float w_sh[64];      // [16][4]
    __shared__ float sc_sh[4], mb_sh[4], zb_sh[4];

    int t = threadIdx.x, lane = t & 31, w = t >> 5;

    if (t < 4) { mb_sh[t] = -1e30f; zb_sh[t] = 0.f; }

    // v in registers: lane owns dims lane*4..+3 and 128+lane*4..+3
    float vr[4][8];
    #pragma unroll
    for (int h = 0; h < 4; h++) {
        float4 va = *(const float4*)(g_v + h * 256 + lane * 4);
        float4 vb = *(const float4*)(g_v + h * 256 + 128 + lane * 4);
        vr[h][0] = va.x; vr[h][1] = va.y; vr[h][2] = va.z; vr[h][3] = va.w;
        vr[h][4] = vb.x; vr[h][5] = vb.y; vr[h][6] = vb.z; vr[h][7] = vb.w;
    }
    float c0 = g_c[0], c1 = g_c[1], c2 = g_c[2], c3 = g_c[3];

    float acc[4] = {0.f, 0.f, 0.f, 0.f};

    // tile load: thread t -> row t>>4, 4 x 16B chunks at cols (t&15)*16 + 4k
    int lrow = t >> 4, lcol = (t & 15) * 16;

    int tile = blockIdx.x;
    if (tile < NT) {
        const float* src = code + (size_t)tile * ROWS * 256 + lrow * 256 + lcol;
        float* dst = &buf[0][lrow * 256 + lcol];
        #pragma unroll
        for (int k = 0; k < 4; k++) cp_async16(dst + k * 4, src + k * 4);
    }
    cp_commit();

    int cur = 0;
    for (; tile < NT; tile += GRID) {
        __syncthreads();                       // prior reads of buf[cur^1] done
        int nxt = tile + GRID;
        if (nxt < NT) {
            const float* src = code + (size_t)nxt * ROWS * 256 + lrow * 256 + lcol;
            float* dst = &buf[cur ^ 1][lrow * 256 + lcol];
            #pragma unroll
            for (int k = 0; k < 4; k++) cp_async16(dst + k * 4, src + k * 4);
        }
        cp_commit();
        cp_wait1();                            // buf[cur]'s group complete
        __syncthreads();

        // ---- stage C: scores for 16 codes ----
        #pragma unroll
        for (int cc = 0; cc < 2; cc++) {
            int row = w * 2 + cc;
            float4 ca = *(const float4*)&buf[cur][row * 256 + lane * 4];
            float4 cb = *(const float4*)&buf[cur][row * 256 + 128 + lane * 4];
            float e[4];
            #pragma unroll
            for (int h = 0; h < 4; h++) {
                e[h] = vr[h][0] * ca.x + vr[h][1] * ca.y + vr[h][2] * ca.z + vr[h][3] * ca.w
                     + vr[h][4] * cb.x + vr[h][5] * cb.y + vr[h][6] * cb.z + vr[h][7] * cb.w;
            }
            #pragma unroll
            for (int o = 16; o; o >>= 1) {
                #pragma unroll
                for (int h = 0; h < 4; h++) e[h] += __shfl_xor_sync(0xffffffffu, e[h], o);
            }
            e[0] += c0; e[1] += c1; e[2] += c2; e[3] += c3;
            #pragma unroll
            for (int h = 0; h < 4; h++) e[h] = e[h] >= 0.f ? e[h] : 0.2f * e[h];
            if (lane == 0) {
                #pragma unroll
                for (int h = 0; h < 4; h++) e_sh[h * 16 + row] = e[h];
            }
        }
        __syncthreads();

        // ---- stage M: online softmax bookkeeping (warp 0) ----
        if (w == 0) {
            int g = lane >> 3, j = lane & 7;   // g = head, 8 lanes per head
            float v1 = e_sh[g * 16 + j];
            float v2 = e_sh[g * 16 + j + 8];
            float mx = fmaxf(v1, v2);
            mx = fmaxf(mx, __shfl_xor_sync(0xffffffffu, mx, 1));
            mx = fmaxf(mx, __shfl_xor_sync(0xffffffffu, mx, 2));
            mx = fmaxf(mx, __shfl_xor_sync(0xffffffffu, mx, 4));
            float mold = mb_sh[g];
            float nm = fmaxf(mold, mx);
            float sc = exp2f((mold - nm) * L2E);
            float w1 = exp2f((v1 - nm) * L2E);
            float w2 = exp2f((v2 - nm) * L2E);
            w_sh[j * 4 + g] = w1;
            w_sh[(j + 8) * 4 + g] = w2;
            float zt = w1 + w2;
            zt += __shfl_xor_sync(0xffffffffu, zt, 1);
            zt += __shfl_xor_sync(0xffffffffu, zt, 2);
            zt += __shfl_xor_sync(0xffffffffu, zt, 4);
            if (j == 0) {
                mb_sh[g] = nm;
                sc_sh[g] = sc;
                zb_sh[g] = zb_sh[g] * sc + zt;
            }
        }
        __syncthreads();

        // ---- stage G: weighted accumulation (thread t owns dim t) ----
        float s0 = sc_sh[0], s1 = sc_sh[1], s2 = sc_sh[2], s3 = sc_sh[3];
        acc[0] *= s0; acc[1] *= s1; acc[2] *= s2; acc[3] *= s3;
        #pragma unroll
        for (int j = 0; j < ROWS; j++) {
            float4 ww = *(const float4*)&w_sh[j * 4];
            float x = buf[cur][j * 256 + t];
            acc[0] = fmaf(ww.x, x, acc[0]);
            acc[1] = fmaf(ww.y, x, acc[1]);
            acc[2] = fmaf(ww.z, x, acc[2]);
            acc[3] = fmaf(ww.w, x, acc[3]);
        }
        cur ^= 1;
    }

    __syncthreads();
    #pragma unroll
    for (int h = 0; h < 4; h++)
        g_partB[((size_t)blockIdx.x * 4 + h) * 256 + t] = acc[h];
    if (t < 4) {
        g_mb[blockIdx.x * 4 + t] = mb_sh[t];
        g_zb[blockIdx.x * 4 + t] = zb_sh[t];
    }
}

// ---------------- K3: combine partials + agg projection ----------------------
__global__ void k_agg(const float* __restrict__ W, const float* __restrict__ bb,
                      float* __restrict__ out) {
    int h = blockIdx.x, t = threadIdx.x;
    __shared__ float scale_sh[GRID];
    __shared__ float red[256];
    __shared__ float agg_sh[256];

    // global max
    float lm = -1e30f;
    for (int b = t; b < GRID; b += 256) lm = fmaxf(lm, g_mb[b * 4 + h]);
    red[t] = lm;
    __syncthreads();
    for (int o = 128; o; o >>= 1) {
        if (t < o) red[t] = fmaxf(red[t], red[t + o]);
        __syncthreads();
    }
    float M = red[0];
    __syncthreads();

    // scales + Z
    float lz = 0.f;
    for (int b = t; b < GRID; b += 256) {
        float s = exp2f((g_mb[b * 4 + h] - M) * L2E);
        scale_sh[b] = s;
        lz += g_zb[b * 4 + h] * s;
    }
    red[t] = lz;
    __syncthreads();
    for (int o = 128; o; o >>= 1) {
        if (t < o) red[t] += red[t + o];
        __syncthreads();
    }
    float invZ = 1.0f / red[0];

    // weighted code sum, normalized
    float s_d = 0.f;
    for (int b = 0; b < GRID; b++)
        s_d = fmaf(g_partB[((size_t)b * 4 + h) * 256 + t], scale_sh[b], s_d);
    agg_sh[t] = s_d * invZ;
    __syncthreads();

    // project: mho[h][k] = agg[h] @ W[h][:,k] + b[h][k]
    if (t < 128) {
        float acc = bb[h * 128 + t];
        const float* wp = W + (size_t)h * 256 * 128 + t;
        #pragma unroll 8
        for (int d = 0; d < 256; d++) acc = fmaf(agg_sh[d], wp[(size_t)d * 128], acc);
        g_mho[h * 128 + t] = acc;
        out[256 + h * 128 + t] = acc;
    }
}

// ---------------- K4: specialty logits ---------------------------------------
__global__ void k_logits(const float* __restrict__ Wc, const float* __restrict__ bc,
                         float* __restrict__ out) {
    int wid = threadIdx.x >> 5, lane = threadIdx.x & 31;
    int j = blockIdx.x * 4 + wid;
    const float4* wp = (const float4*)(Wc + (size_t)j * 512);
    const float4* mp = (const float4*)g_mho;
    float acc = 0.f;
    #pragma unroll 4
    for (int q = lane; q < 128; q += 32) {
        float4 w = wp[q], m = mp[q];
        acc += w.x * m.x + w.y * m.y + w.z * m.z + w.w * m.w;
    }
    #pragma unroll
    for (int o = 16; o; o >>= 1) acc += __shfl_xor_sync(0xffffffffu, acc, o);
    if (lane == 0) out[j] = acc + bc[j];
}

// ---------------- launch ------------------------------------------------------
extern "C" void kernel_launch(void* const* d_in, const int* in_sizes, int n_in,
                              void* d_out, int out_size) {
    const float* p    = (const float*)d_in[0];
    const float* code = (const float*)d_in[1];
    const float* W    = (const float*)d_in[2];
    const float* bb   = (const float*)d_in[3];
    const float* a    = (const float*)d_in[4];
    const float* Wc   = (const float*)d_in[5];
    const float* bc   = (const float*)d_in[6];
    float* out = (float*)d_out;

    k_prep  <<<12,   128>>>(W, a, p, bb);
    k_fused <<<GRID, 256>>>(code);
    k_agg   <<<4,    256>>>(W, bb, out);
    k_logits<<<64,   128>>>(Wc, bc, out);
}

// round 4
// speedup vs baseline: 1.6800x; 1.4022x over previous
#include <cuda_runtime.h>
#include <cstdint>

#define N_CODES 100000
#define CODE_DIM 256
#define HIDDEN 128
#define HEADS 4
#define N_SPEC 256

#define GRID 296               // 2 blocks/SM on 148 SMs, one wave
#define NW (GRID * 8)          // 2368 warps, ~42 rows each
#define DEPTH 6                // per-warp cp.async pipeline depth (rows)
#define L2E 1.4426950408889634f

// ---------------- scratch (device globals) ----------------------------------
__device__ __align__(16) float g_v[HEADS * CODE_DIM];
__device__ float g_c[HEADS];
__device__ __align__(16) float g_partB[GRID * HEADS * CODE_DIM];
__device__ float g_mb[GRID * HEADS];
__device__ float g_zb[GRID * HEADS];
__device__ __align__(16) float g_mho[HEADS * HIDDEN];

// ---------------- K1: prep ---------------------------------------------------
__global__ void k_prep(const float* __restrict__ W, const float* __restrict__ a,
                       const float* __restrict__ p, const float* __restrict__ bb) {
    if (blockIdx.x < 8) {
        int idx = blockIdx.x * 128 + threadIdx.x;   // 0..1023
        int h = idx >> 8, d = idx & 255;
        const float4* wr = (const float4*)(W + (size_t)(h * 256 + d) * 128);
        const float4* a2 = (const float4*)(a + h * 256 + 128);
        float acc = 0.f;
        #pragma unroll
        for (int q = 0; q < 32; q++) {
            float4 w = wr[q], x = a2[q];
            acc += w.x * x.x + w.y * x.y + w.z * x.z + w.w * x.w;
        }
        g_v[idx] = acc;
    } else {
        int h = blockIdx.x - 8;
        int k = threadIdx.x;
        float ph = bb[h * 128 + k];
        const float* wp = W + (size_t)h * 256 * 128 + k;
        for (int d = 0; d < 256; d++) ph = fmaf(p[d], wp[(size_t)d * 128], ph);
        float val = ph * a[h * 256 + k] + bb[h * 128 + k] * a[h * 256 + 128 + k];
        __shared__ float red[128];
        red[k] = val;
        __syncthreads();
        for (int o = 64; o; o >>= 1) {
            if (k < o) red[k] += red[k + o];
            __syncthreads();
        }
        if (k == 0) g_c[h] = red[0];
    }
}

// ---------------- cp.async helpers ------------------------------------------
__device__ __forceinline__ void cp_async16(void* smem, const void* gmem) {
    uint32_t s = (uint32_t)__cvta_generic_to_shared(smem);
    asm volatile("cp.async.cg.shared.global [%0], [%1], 16;\n" :: "r"(s), "l"(gmem));
}
__device__ __forceinline__ void cp_commit() {
    asm volatile("cp.async.commit_group;\n" ::: "memory");
}
template<int N> __device__ __forceinline__ void cp_wait() {
    asm volatile("cp.async.wait_group %0;\n" :: "n"(N) : "memory");
}

// ---------------- K2: fused single-pass, warp-autonomous ---------------------
// Each warp: rows n = gw + i*NW. Per row: lane stages its own 32B via cp.async
// (6-deep pipeline), computes 4 head-dots (butterfly => uniform), warp-uniform
// online softmax (rare rescale branch), accumulates weighted sum from the same
// registers. No __syncthreads until the final block combine.
__global__ void __launch_bounds__(256, 2) k_fused(const float* __restrict__ code) {
    __shared__ float buf[8][DEPTH * 256];          // 48 KB: 8 warps x 6 x 1KB
    __shared__ float cm[8][4], cz[8][4], csc[8][4];

    int t = threadIdx.x, lane = t & 31, w = t >> 5;
    int gw = blockIdx.x * 8 + w;
    int cnt = (N_CODES - gw + NW - 1) / NW;        // rows for this warp (42/43)

    float* bw = &buf[w][0];
    const float* base = code + (size_t)gw * 256;

    // v in registers: lane owns dims [lane*4, +4) and [128+lane*4, +4)
    float vr[4][8];
    #pragma unroll
    for (int h = 0; h < 4; h++) {
        float4 va = *(const float4*)(g_v + h * 256 + lane * 4);
        float4 vb = *(const float4*)(g_v + h * 256 + 128 + lane * 4);
        vr[h][0] = va.x; vr[h][1] = va.y; vr[h][2] = va.z; vr[h][3] = va.w;
        vr[h][4] = vb.x; vr[h][5] = vb.y; vr[h][6] = vb.z; vr[h][7] = vb.w;
    }
    float c0 = g_c[0], c1 = g_c[1], c2 = g_c[2], c3 = g_c[3];

    float m0 = -1e30f, m1 = -1e30f, m2 = -1e30f, m3 = -1e30f;
    float s0 = 0.f, s1 = 0.f, s2 = 0.f, s3 = 0.f;
    float acc[4][8];
    #pragma unroll
    for (int h = 0; h < 4; h++)
        #pragma unroll
        for (int k = 0; k < 8; k++) acc[h][k] = 0.f;

    // prologue: issue rows 0..DEPTH-2 (one commit group per row)
    #pragma unroll
    for (int k = 0; k < DEPTH - 1; k++) {
        if (k < cnt) {
            const float* src = base + (size_t)k * NW * 256;
            cp_async16(bw + k * 256 + lane * 4, src + lane * 4);
            cp_async16(bw + k * 256 + 128 + lane * 4, src + 128 + lane * 4);
        }
        cp_commit();
    }

    for (int i = 0; i < cnt; i++) {
        cp_wait<DEPTH - 2>();                      // row i's group complete
        int slot = i % DEPTH;
        float4 x0 = *(const float4*)(bw + slot * 256 + lane * 4);
        float4 x1 = *(const float4*)(bw + slot * 256 + 128 + lane * 4);

        // issue row i+DEPTH-1 into slot consumed at iteration i-1
        int j = i + DEPTH - 1;
        if (j < cnt) {
            const float* src = base + (size_t)j * NW * 256;
            int js = j % DEPTH;
            cp_async16(bw + js * 256 + lane * 4, src + lane * 4);
            cp_async16(bw + js * 256 + 128 + lane * 4, src + 128 + lane * 4);
        }
        cp_commit();

        // 4 head-dots from registers
        float e0 = vr[0][0]*x0.x + vr[0][1]*x0.y + vr[0][2]*x0.z + vr[0][3]*x0.w
                 + vr[0][4]*x1.x + vr[0][5]*x1.y + vr[0][6]*x1.z + vr[0][7]*x1.w;
        float e1 = vr[1][0]*x0.x + vr[1][1]*x0.y + vr[1][2]*x0.z + vr[1][3]*x0.w
                 + vr[1][4]*x1.x + vr[1][5]*x1.y + vr[1][6]*x1.z + vr[1][7]*x1.w;
        float e2 = vr[2][0]*x0.x + vr[2][1]*x0.y + vr[2][2]*x0.z + vr[2][3]*x0.w
                 + vr[2][4]*x1.x + vr[2][5]*x1.y + vr[2][6]*x1.z + vr[2][7]*x1.w;
        float e3 = vr[3][0]*x0.x + vr[3][1]*x0.y + vr[3][2]*x0.z + vr[3][3]*x0.w
                 + vr[3][4]*x1.x + vr[3][5]*x1.y + vr[3][6]*x1.z + vr[3][7]*x1.w;
        #pragma unroll
        for (int o = 16; o; o >>= 1) {
            e0 += __shfl_xor_sync(0xffffffffu, e0, o);
            e1 += __shfl_xor_sync(0xffffffffu, e1, o);
            e2 += __shfl_xor_sync(0xffffffffu, e2, o);
            e3 += __shfl_xor_sync(0xffffffffu, e3, o);
        }
        e0 += c0; e1 += c1; e2 += c2; e3 += c3;
        e0 = e0 >= 0.f ? e0 : 0.2f * e0;
        e1 = e1 >= 0.f ? e1 : 0.2f * e1;
        e2 = e2 >= 0.f ? e2 : 0.2f * e2;
        e3 = e3 >= 0.f ? e3 : 0.2f * e3;

        // warp-uniform online softmax; rescale branch taken rarely
        float n0 = fmaxf(m0, e0), n1 = fmaxf(m1, e1);
        float n2 = fmaxf(m2, e2), n3 = fmaxf(m3, e3);
        if (n0 > m0 || n1 > m1 || n2 > m2 || n3 > m3) {
            float r0 = exp2f((m0 - n0) * L2E), r1 = exp2f((m1 - n1) * L2E);
            float r2 = exp2f((m2 - n2) * L2E), r3 = exp2f((m3 - n3) * L2E);
            s0 *= r0; s1 *= r1; s2 *= r2; s3 *= r3;
            #pragma unroll
            for (int k = 0; k < 8; k++) {
                acc[0][k] *= r0; acc[1][k] *= r1;
                acc[2][k] *= r2; acc[3][k] *= r3;
            }
            m0 = n0; m1 = n1; m2 = n2; m3 = n3;
        }
        float w0 = exp2f((e0 - m0) * L2E), w1 = exp2f((e1 - m1) * L2E);
        float w2 = exp2f((e2 - m2) * L2E), w3 = exp2f((e3 - m3) * L2E);
        s0 += w0; s1 += w1; s2 += w2; s3 += w3;

        acc[0][0]=fmaf(w0,x0.x,acc[0][0]); acc[0][1]=fmaf(w0,x0.y,acc[0][1]);
        acc[0][2]=fmaf(w0,x0.z,acc[0][2]); acc[0][3]=fmaf(w0,x0.w,acc[0][3]);
        acc[0][4]=fmaf(w0,x1.x,acc[0][4]); acc[0][5]=fmaf(w0,x1.y,acc[0][5]);
        acc[0][6]=fmaf(w0,x1.z,acc[0][6]); acc[0][7]=fmaf(w0,x1.w,acc[0][7]);
        acc[1][0]=fmaf(w1,x0.x,acc[1][0]); acc[1][1]=fmaf(w1,x0.y,acc[1][1]);
        acc[1][2]=fmaf(w1,x0.z,acc[1][2]); acc[1][3]=fmaf(w1,x0.w,acc[1][3]);
        acc[1][4]=fmaf(w1,x1.x,acc[1][4]); acc[1][5]=fmaf(w1,x1.y,acc[1][5]);
        acc[1][6]=fmaf(w1,x1.z,acc[1][6]); acc[1][7]=fmaf(w1,x1.w,acc[1][7]);
        acc[2][0]=fmaf(w2,x0.x,acc[2][0]); acc[2][1]=fmaf(w2,x0.y,acc[2][1]);
        acc[2][2]=fmaf(w2,x0.z,acc[2][2]); acc[2][3]=fmaf(w2,x0.w,acc[2][3]);
        acc[2][4]=fmaf(w2,x1.x,acc[2][4]); acc[2][5]=fmaf(w2,x1.y,acc[2][5]);
        acc[2][6]=fmaf(w2,x1.z,acc[2][6]); acc[2][7]=fmaf(w2,x1.w,acc[2][7]);
        acc[3][0]=fmaf(w3,x0.x,acc[3][0]); acc[3][1]=fmaf(w3,x0.y,acc[3][1]);
        acc[3][2]=fmaf(w3,x0.z,acc[3][2]); acc[3][3]=fmaf(w3,x0.w,acc[3][3]);
        acc[3][4]=fmaf(w3,x1.x,acc[3][4]); acc[3][5]=fmaf(w3,x1.y,acc[3][5]);
        acc[3][6]=fmaf(w3,x1.z,acc[3][6]); acc[3][7]=fmaf(w3,x1.w,acc[3][7]);
    }
    cp_wait<0>();

    // ---- block combine (once) ----
    if (lane == 0) {
        cm[w][0] = m0; cm[w][1] = m1; cm[w][2] = m2; cm[w][3] = m3;
        cz[w][0] = s0; cz[w][1] = s1; cz[w][2] = s2; cz[w][3] = s3;
    }
    __syncthreads();
    if (t < 32) {
        int wp = t >> 2, h = t & 3;
        float mv = cm[wp][h];
        float M = mv;
        M = fmaxf(M, __shfl_xor_sync(0xffffffffu, M, 4));
        M = fmaxf(M, __shfl_xor_sync(0xffffffffu, M, 8));
        M = fmaxf(M, __shfl_xor_sync(0xffffffffu, M, 16));
        float sc = exp2f((mv - M) * L2E);
        csc[wp][h] = sc;
        float z = cz[wp][h] * sc;
        z += __shfl_xor_sync(0xffffffffu, z, 4);
        z += __shfl_xor_sync(0xffffffffu, z, 8);
        z += __shfl_xor_sync(0xffffffffu, z, 16);
        if (t < 4) { g_mb[blockIdx.x * 4 + h] = M; g_zb[blockIdx.x * 4 + h] = z; }
    }
    __syncthreads();
    // rescale and stage per-warp accs into this warp's buf region [h][256]
    #pragma unroll
    for (int h = 0; h < 4; h++) {
        float sc = csc[w][h];
        *(float4*)(bw + h * 256 + lane * 4) =
            make_float4(acc[h][0]*sc, acc[h][1]*sc, acc[h][2]*sc, acc[h][3]*sc);
        *(float4*)(bw + h * 256 + 128 + lane * 4) =
            make_float4(acc[h][4]*sc, acc[h][5]*sc, acc[h][6]*sc, acc[h][7]*sc);
    }
    __syncthreads();
    // thread t sums dim t over 8 warps for each head
    #pragma unroll
    for (int h = 0; h < 4; h++) {
        float v = 0.f;
        #pragma unroll
        for (int w2 = 0; w2 < 8; w2++) v += buf[w2][h * 256 + t];
        g_partB[((size_t)blockIdx.x * 4 + h) * 256 + t] = v;
    }
}

// ---------------- K3: combine partials + agg projection ----------------------
__global__ void k_agg(const float* __restrict__ W, const float* __restrict__ bb,
                      float* __restrict__ out) {
    int h = blockIdx.x, t = threadIdx.x;
    __shared__ float scale_sh[GRID];
    __shared__ float red[256];
    __shared__ float agg_sh[256];

    float lm = -1e30f;
    for (int b = t; b < GRID; b += 256) lm = fmaxf(lm, g_mb[b * 4 + h]);
    red[t] = lm;
    __syncthreads();
    for (int o = 128; o; o >>= 1) {
        if (t < o) red[t] = fmaxf(red[t], red[t + o]);
        __syncthreads();
    }
    float M = red[0];
    __syncthreads();

    float lz = 0.f;
    for (int b = t; b < GRID; b += 256) {
        float s = exp2f((g_mb[b * 4 + h] - M) * L2E);
        scale_sh[b] = s;
        lz += g_zb[b * 4 + h] * s;
    }
    red[t] = lz;
    __syncthreads();
    for (int o = 128; o; o >>= 1) {
        if (t < o) red[t] += red[t + o];
        __syncthreads();
    }
    float invZ = 1.0f / red[0];

    float s_d = 0.f;
    for (int b = 0; b < GRID; b++)
        s_d = fmaf(g_partB[((size_t)b * 4 + h) * 256 + t], scale_sh[b], s_d);
    agg_sh[t] = s_d * invZ;
    __syncthreads();

    if (t < 128) {
        float acc = bb[h * 128 + t];
        const float* wp = W + (size_t)h * 256 * 128 + t;
        #pragma unroll 8
        for (int d = 0; d < 256; d++) acc = fmaf(agg_sh[d], wp[(size_t)d * 128], acc);
        g_mho[h * 128 + t] = acc;
        out[256 + h * 128 + t] = acc;
    }
}

// ---------------- K4: specialty logits ---------------------------------------
__global__ void k_logits(const float* __restrict__ Wc, const float* __restrict__ bc,
                         float* __restrict__ out) {
    int wid = threadIdx.x >> 5, lane = threadIdx.x & 31;
    int j = blockIdx.x * 4 + wid;
    const float4* wp = (const float4*)(Wc + (size_t)j * 512);
    const float4* mp = (const float4*)g_mho;
    float acc = 0.f;
    #pragma unroll 4
    for (int q = lane; q < 128; q += 32) {
        float4 w = wp[q], m = mp[q];
        acc += w.x * m.x + w.y * m.y + w.z * m.z + w.w * m.w;
    }
    #pragma unroll
    for (int o = 16; o; o >>= 1) acc += __shfl_xor_sync(0xffffffffu, acc, o);
    if (lane == 0) out[j] = acc + bc[j];
}

// ---------------- launch ------------------------------------------------------
extern "C" void kernel_launch(void* const* d_in, const int* in_sizes, int n_in,
                              void* d_out, int out_size) {
    const float* p    = (const float*)d_in[0];
    const float* code = (const float*)d_in[1];
    const float* W    = (const float*)d_in[2];
    const float* bb   = (const float*)d_in[3];
    const float* a    = (const float*)d_in[4];
    const float* Wc   = (const float*)d_in[5];
    const float* bc   = (const float*)d_in[6];
    float* out = (float*)d_out;

    k_prep  <<<12,   128>>>(W, a, p, bb);
    k_fused <<<GRID, 256>>>(code);
    k_agg   <<<4,    256>>>(W, bb, out);
    k_logits<<<64,   128>>>(Wc, bc, out);
}

// round 5
// speedup vs baseline: 1.7203x; 1.0240x over previous
#include <cuda_runtime.h>
#include <cstdint>
#include <cooperative_groups.h>
#include <cooperative_groups/reduce.h>
namespace cg = cooperative_groups;

#define N_CODES 100000
#define CODE_DIM 256
#define HIDDEN 128
#define HEADS 4
#define N_SPEC 256

#define GRID 296               // 2 blocks/SM on 148 SMs, one wave
#define NW (GRID * 8)          // 2368 warps, ~42 rows each
#define DEPTH 8                // per-warp cp.async pipeline depth (rows)
#define L2E 1.4426950408889634f

// ---------------- scratch (device globals) ----------------------------------
__device__ __align__(16) float g_v[HEADS * CODE_DIM];   // W[h]@a2[h]
__device__ __align__(16) float g_u[HEADS * CODE_DIM];   // W[h]@a1[h]
__device__ float g_c[HEADS];
__device__ __align__(16) float g_partB[GRID * HEADS * CODE_DIM];
__device__ float g_mb[GRID * HEADS];
__device__ float g_zb[GRID * HEADS];
__device__ __align__(16) float g_mho[HEADS * HIDDEN];

// ---------------- f32x2 helpers (Blackwell packed fp32) ----------------------
__device__ __forceinline__ uint64_t fma2(uint64_t a, uint64_t b, uint64_t c) {
    uint64_t d;
    asm("fma.rn.f32x2 %0, %1, %2, %3;" : "=l"(d) : "l"(a), "l"(b), "l"(c));
    return d;
}
__device__ __forceinline__ uint64_t mul2(uint64_t a, uint64_t b) {
    uint64_t d;
    asm("mul.rn.f32x2 %0, %1, %2;" : "=l"(d) : "l"(a), "l"(b));
    return d;
}
__device__ __forceinline__ uint64_t pack2(float x) {
    uint64_t d;
    asm("mov.b64 %0, {%1, %1};" : "=l"(d) : "f"(x));
    return d;
}
__device__ __forceinline__ float2 unpack2(uint64_t p) {
    uint32_t lo, hi;
    asm("mov.b64 {%0, %1}, %2;" : "=r"(lo), "=r"(hi) : "l"(p));
    return make_float2(__uint_as_float(lo), __uint_as_float(hi));
}

// ---------------- cp.async helpers ------------------------------------------
__device__ __forceinline__ void cp_async16(void* smem, const void* gmem) {
    uint32_t s = (uint32_t)__cvta_generic_to_shared(smem);
    asm volatile("cp.async.cg.shared.global [%0], [%1], 16;\n" :: "r"(s), "l"(gmem));
}
__device__ __forceinline__ void cp_commit() {
    asm volatile("cp.async.commit_group;\n" ::: "memory");
}
template<int N> __device__ __forceinline__ void cp_wait() {
    asm volatile("cp.async.wait_group %0;\n" :: "n"(N) : "memory");
}

// ---------------- K1a: u,v projections (fully coalesced) ---------------------
__global__ void k_prep(const float* __restrict__ W, const float* __restrict__ a) {
    int idx = blockIdx.x * 128 + threadIdx.x;   // 0..1023 = (h,d)
    int h = idx >> 8;
    const float4* wr = (const float4*)(W + (size_t)idx * 128);
    const float4* a1 = (const float4*)(a + h * 256);
    const float4* a2 = (const float4*)(a + h * 256 + 128);
    float av = 0.f, au = 0.f;
    #pragma unroll
    for (int q = 0; q < 32; q++) {
        float4 w = wr[q], x1 = a1[q], x2 = a2[q];
        au += w.x * x1.x + w.y * x1.y + w.z * x1.z + w.w * x1.w;
        av += w.x * x2.x + w.y * x2.y + w.z * x2.z + w.w * x2.w;
    }
    g_v[idx] = av;
    g_u[idx] = au;
}

// ---------------- K1b: score constants c[h] ----------------------------------
__global__ void k_prep2(const float* __restrict__ a, const float* __restrict__ p,
                        const float* __restrict__ bb) {
    int h = threadIdx.x >> 5, lane = threadIdx.x & 31;
    auto warp = cg::tiled_partition<32>(cg::this_thread_block());
    float s = 0.f;
    for (int d = lane; d < 256; d += 32) s += p[d] * g_u[h * 256 + d];
    for (int k = lane; k < 128; k += 32)
        s += bb[h * 128 + k] * (a[h * 256 + k] + a[h * 256 + 128 + k]);
    s = cg::reduce(warp, s, cg::plus<float>());
    if (lane == 0) g_c[h] = s;
}

// ---------------- K2: fused single-pass, warp-autonomous, f32x2 --------------
__global__ void __launch_bounds__(256, 2) k_fused(const float* __restrict__ code) {
    __shared__ float buf[8][DEPTH * 256];          // 64 KB: 8 warps x 8 x 1KB
    __shared__ float cm[8][4], cz[8][4], csc[8][4];

    int t = threadIdx.x, lane = t & 31, w = t >> 5;
    int gw = blockIdx.x * 8 + w;
    int cnt = (N_CODES - gw + NW - 1) / NW;
    auto warp = cg::tiled_partition<32>(cg::this_thread_block());

    float* bw = &buf[w][0];
    const float* base = code + (size_t)gw * 256;

    // v packed: lane owns dims [lane*4,+4) and [128+lane*4,+4) as 4 f32x2 each head
    uint64_t vp[4][4];
    #pragma unroll
    for (int h = 0; h < 4; h++) {
        ulonglong2 va = *(const ulonglong2*)(g_v + h * 256 + lane * 4);
        ulonglong2 vb = *(const ulonglong2*)(g_v + h * 256 + 128 + lane * 4);
        vp[h][0] = va.x; vp[h][1] = va.y; vp[h][2] = vb.x; vp[h][3] = vb.y;
    }
    float c0 = g_c[0], c1 = g_c[1], c2 = g_c[2], c3 = g_c[3];

    float m0 = -1e30f, m1 = -1e30f, m2 = -1e30f, m3 = -1e30f;
    float s0 = 0.f, s1 = 0.f, s2 = 0.f, s3 = 0.f;
    uint64_t acc[4][4];
    #pragma unroll
    for (int h = 0; h < 4; h++)
        #pragma unroll
        for (int k = 0; k < 4; k++) acc[h][k] = 0ull;

    // prologue
    #pragma unroll
    for (int k = 0; k < DEPTH - 1; k++) {
        if (k < cnt) {
            const float* src = base + (size_t)k * NW * 256;
            cp_async16(bw + k * 256 + lane * 4, src + lane * 4);
            cp_async16(bw + k * 256 + 128 + lane * 4, src + 128 + lane * 4);
        }
        cp_commit();
    }

    for (int i = 0; i < cnt; i++) {
        cp_wait<DEPTH - 2>();
        int slot = i % DEPTH;
        ulonglong2 xa = *(const ulonglong2*)(bw + slot * 256 + lane * 4);
        ulonglong2 xb = *(const ulonglong2*)(bw + slot * 256 + 128 + lane * 4);

        int j = i + DEPTH - 1;
        if (j < cnt) {
            const float* src = base + (size_t)j * NW * 256;
            int js = j % DEPTH;
            cp_async16(bw + js * 256 + lane * 4, src + lane * 4);
            cp_async16(bw + js * 256 + 128 + lane * 4, src + 128 + lane * 4);
        }
        cp_commit();

        // packed dots: 4 f32x2 FMAs per head
        uint64_t d0 = mul2(vp[0][0], xa.x);
        uint64_t d1 = mul2(vp[1][0], xa.x);
        uint64_t d2 = mul2(vp[2][0], xa.x);
        uint64_t d3 = mul2(vp[3][0], xa.x);
        d0 = fma2(vp[0][1], xa.y, d0); d1 = fma2(vp[1][1], xa.y, d1);
        d2 = fma2(vp[2][1], xa.y, d2); d3 = fma2(vp[3][1], xa.y, d3);
        d0 = fma2(vp[0][2], xb.x, d0); d1 = fma2(vp[1][2], xb.x, d1);
        d2 = fma2(vp[2][2], xb.x, d2); d3 = fma2(vp[3][2], xb.x, d3);
        d0 = fma2(vp[0][3], xb.y, d0); d1 = fma2(vp[1][3], xb.y, d1);
        d2 = fma2(vp[2][3], xb.y, d2); d3 = fma2(vp[3][3], xb.y, d3);
        float2 f0 = unpack2(d0), f1 = unpack2(d1), f2 = unpack2(d2), f3 = unpack2(d3);
        float e0 = f0.x + f0.y, e1 = f1.x + f1.y;
        float e2 = f2.x + f2.y, e3 = f3.x + f3.y;

        // warp reduce (REDUX.F32 on sm_103a via cg)
        e0 = cg::reduce(warp, e0, cg::plus<float>());
        e1 = cg::reduce(warp, e1, cg::plus<float>());
        e2 = cg::reduce(warp, e2, cg::plus<float>());
        e3 = cg::reduce(warp, e3, cg::plus<float>());

        e0 += c0; e1 += c1; e2 += c2; e3 += c3;
        e0 = e0 >= 0.f ? e0 : 0.2f * e0;
        e1 = e1 >= 0.f ? e1 : 0.2f * e1;
        e2 = e2 >= 0.f ? e2 : 0.2f * e2;
        e3 = e3 >= 0.f ? e3 : 0.2f * e3;

        // warp-uniform online softmax; rescale branch rare
        float n0 = fmaxf(m0, e0), n1 = fmaxf(m1, e1);
        float n2 = fmaxf(m2, e2), n3 = fmaxf(m3, e3);
        if (n0 > m0 || n1 > m1 || n2 > m2 || n3 > m3) {
            float r0 = exp2f((m0 - n0) * L2E), r1 = exp2f((m1 - n1) * L2E);
            float r2 = exp2f((m2 - n2) * L2E), r3 = exp2f((m3 - n3) * L2E);
            s0 *= r0; s1 *= r1; s2 *= r2; s3 *= r3;
            uint64_t q0 = pack2(r0), q1 = pack2(r1), q2 = pack2(r2), q3 = pack2(r3);
            #pragma unroll
            for (int k = 0; k < 4; k++) {
                acc[0][k] = mul2(q0, acc[0][k]); acc[1][k] = mul2(q1, acc[1][k]);
                acc[2][k] = mul2(q2, acc[2][k]); acc[3][k] = mul2(q3, acc[3][k]);
            }
            m0 = n0; m1 = n1; m2 = n2; m3 = n3;
        }
        float w0 = exp2f((e0 - m0) * L2E), w1 = exp2f((e1 - m1) * L2E);
        float w2 = exp2f((e2 - m2) * L2E), w3 = exp2f((e3 - m3) * L2E);
        s0 += w0; s1 += w1; s2 += w2; s3 += w3;
        uint64_t p0 = pack2(w0), p1 = pack2(w1), p2 = pack2(w2), p3 = pack2(w3);

        acc[0][0] = fma2(p0, xa.x, acc[0][0]); acc[0][1] = fma2(p0, xa.y, acc[0][1]);
        acc[0][2] = fma2(p0, xb.x, acc[0][2]); acc[0][3] = fma2(p0, xb.y, acc[0][3]);
        acc[1][0] = fma2(p1, xa.x, acc[1][0]); acc[1][1] = fma2(p1, xa.y, acc[1][1]);
        acc[1][2] = fma2(p1, xb.x, acc[1][2]); acc[1][3] = fma2(p1, xb.y, acc[1][3]);
        acc[2][0] = fma2(p2, xa.x, acc[2][0]); acc[2][1] = fma2(p2, xa.y, acc[2][1]);
        acc[2][2] = fma2(p2, xb.x, acc[2][2]); acc[2][3] = fma2(p2, xb.y, acc[2][3]);
        acc[3][0] = fma2(p3, xa.x, acc[3][0]); acc[3][1] = fma2(p3, xa.y, acc[3][1]);
        acc[3][2] = fma2(p3, xb.x, acc[3][2]); acc[3][3] = fma2(p3, xb.y, acc[3][3]);
    }
    cp_wait<0>();

    // ---- block combine (once) ----
    if (lane == 0) {
        cm[w][0] = m0; cm[w][1] = m1; cm[w][2] = m2; cm[w][3] = m3;
        cz[w][0] = s0; cz[w][1] = s1; cz[w][2] = s2; cz[w][3] = s3;
    }
    __syncthreads();
    if (t < 32) {
        int wp = t >> 2, h = t & 3;
        float mv = cm[wp][h];
        float M = mv;
        M = fmaxf(M, __shfl_xor_sync(0xffffffffu, M, 4));
        M = fmaxf(M, __shfl_xor_sync(0xffffffffu, M, 8));
        M = fmaxf(M, __shfl_xor_sync(0xffffffffu, M, 16));
        float sc = exp2f((mv - M) * L2E);
        csc[wp][h] = sc;
        float z = cz[wp][h] * sc;
        z += __shfl_xor_sync(0xffffffffu, z, 4);
        z += __shfl_xor_sync(0xffffffffu, z, 8);
        z += __shfl_xor_sync(0xffffffffu, z, 16);
        if (t < 4) { g_mb[blockIdx.x * 4 + h] = M; g_zb[blockIdx.x * 4 + h] = z; }
    }
    __syncthreads();
    #pragma unroll
    for (int h = 0; h < 4; h++) {
        float sc = csc[w][h];
        float2 a0 = unpack2(acc[h][0]), a1 = unpack2(acc[h][1]);
        float2 a2 = unpack2(acc[h][2]), a3 = unpack2(acc[h][3]);
        *(float4*)(bw + h * 256 + lane * 4) =
            make_float4(a0.x * sc, a0.y * sc, a1.x * sc, a1.y * sc);
        *(float4*)(bw + h * 256 + 128 + lane * 4) =
            make_float4(a2.x * sc, a2.y * sc, a3.x * sc, a3.y * sc);
    }
    __syncthreads();
    #pragma unroll
    for (int h = 0; h < 4; h++) {
        float v = 0.f;
        #pragma unroll
        for (int w2 = 0; w2 < 8; w2++) v += buf[w2][h * 256 + t];
        g_partB[((size_t)blockIdx.x * 4 + h) * 256 + t] = v;
    }
}

// ---------------- K3: combine partials + agg projection ----------------------
__global__ void k_agg(const float* __restrict__ W, const float* __restrict__ bb,
                      float* __restrict__ out) {
    int h = blockIdx.x, t = threadIdx.x;
    __shared__ float scale_sh[GRID];
    __shared__ float red[256];
    __shared__ float agg_sh[256];

    float lm = -1e30f;
    for (int b = t; b < GRID; b += 256) lm = fmaxf(lm, g_mb[b * 4 + h]);
    red[t] = lm;
    __syncthreads();
    for (int o = 128; o; o >>= 1) {
        if (t < o) red[t] = fmaxf(red[t], red[t + o]);
        __syncthreads();
    }
    float M = red[0];
    __syncthreads();

    float lz = 0.f;
    for (int b = t; b < GRID; b += 256) {
        float s = exp2f((g_mb[b * 4 + h] - M) * L2E);
        scale_sh[b] = s;
        lz += g_zb[b * 4 + h] * s;
    }
    red[t] = lz;
    __syncthreads();
    for (int o = 128; o; o >>= 1) {
        if (t < o) red[t] += red[t + o];
        __syncthreads();
    }
    float invZ = 1.0f / red[0];

    float s_d = 0.f;
    for (int b = 0; b < GRID; b++)
        s_d = fmaf(g_partB[((size_t)b * 4 + h) * 256 + t], scale_sh[b], s_d);
    agg_sh[t] = s_d * invZ;
    __syncthreads();

    if (t < 128) {
        float acc = bb[h * 128 + t];
        const float* wp = W + (size_t)h * 256 * 128 + t;
        #pragma unroll 8
        for (int d = 0; d < 256; d++) acc = fmaf(agg_sh[d], wp[(size_t)d * 128], acc);
        g_mho[h * 128 + t] = acc;
        out[256 + h * 128 + t] = acc;
    }
}

// ---------------- K4: specialty logits ---------------------------------------
__global__ void k_logits(const float* __restrict__ Wc, const float* __restrict__ bc,
                         float* __restrict__ out) {
    int wid = threadIdx.x >> 5, lane = threadIdx.x & 31;
    int j = blockIdx.x * 2 + wid;
    const float4* wp = (const float4*)(Wc + (size_t)j * 512);
    const float4* mp = (const float4*)g_mho;
    float acc = 0.f;
    #pragma unroll 4
    for (int q = lane; q < 128; q += 32) {
        float4 w = wp[q], m = mp[q];
        acc += w.x * m.x + w.y * m.y + w.z * m.z + w.w * m.w;
    }
    #pragma unroll
    for (int o = 16; o; o >>= 1) acc += __shfl_xor_sync(0xffffffffu, acc, o);
    if (lane == 0) out[j] = acc + bc[j];
}

// ---------------- launch ------------------------------------------------------
extern "C" void kernel_launch(void* const* d_in, const int* in_sizes, int n_in,
                              void* d_out, int out_size) {
    const float* p    = (const float*)d_in[0];
    const float* code = (const float*)d_in[1];
    const float* W    = (const float*)d_in[2];
    const float* bb   = (const float*)d_in[3];
    const float* a    = (const float*)d_in[4];
    const float* Wc   = (const float*)d_in[5];
    const float* bc   = (const float*)d_in[6];
    float* out = (float*)d_out;

    k_prep  <<<8,    128>>>(W, a);
    k_prep2 <<<1,    128>>>(a, p, bb);
    k_fused <<<GRID, 256>>>(code);
    k_agg   <<<4,    256>>>(W, bb, out);
    k_logits<<<128,  64>>>(Wc, bc, out);
}

// round 6
// speedup vs baseline: 1.8304x; 1.0640x over previous
#include <cuda_runtime.h>
#include <cstdint>
#include <cooperative_groups.h>
#include <cooperative_groups/reduce.h>
namespace cg = cooperative_groups;

#define N_CODES 100000
#define CODE_DIM 256
#define HIDDEN 128
#define HEADS 4
#define N_SPEC 256

#define GRID 296               // 2 blocks/SM on 148 SMs, one wave
#define NW (GRID * 8)          // 2368 warps, ~42 rows each
#define DEPTH 8                // per-warp cp.async pipeline depth (rows)
#define L2E 1.4426950408889634f

// ---------------- scratch (device globals) ----------------------------------
__device__ __align__(16) float g_v[HEADS * CODE_DIM];   // W[h]@a2[h]
__device__ __align__(16) float g_u[HEADS * CODE_DIM];   // W[h]@a1[h]
__device__ float g_c[HEADS];
__device__ __align__(16) float g_partB[GRID * HEADS * CODE_DIM];
__device__ float g_mb[GRID * HEADS];
__device__ float g_zb[GRID * HEADS];
__device__ __align__(16) float g_scale[GRID * HEADS];   // exp2(mb-M)/Z folded
__device__ __align__(16) float g_part2[16 * CODE_DIM];  // 4 quarters x 4 heads
__device__ __align__(16) float g_mho[HEADS * HIDDEN];

// ---------------- f32x2 helpers (Blackwell packed fp32) ----------------------
__device__ __forceinline__ uint64_t fma2(uint64_t a, uint64_t b, uint64_t c) {
    uint64_t d;
    asm("fma.rn.f32x2 %0, %1, %2, %3;" : "=l"(d) : "l"(a), "l"(b), "l"(c));
    return d;
}
__device__ __forceinline__ uint64_t mul2(uint64_t a, uint64_t b) {
    uint64_t d;
    asm("mul.rn.f32x2 %0, %1, %2;" : "=l"(d) : "l"(a), "l"(b));
    return d;
}
__device__ __forceinline__ uint64_t pack2(float x) {
    uint64_t d;
    asm("mov.b64 %0, {%1, %1};" : "=l"(d) : "f"(x));
    return d;
}
__device__ __forceinline__ float2 unpack2(uint64_t p) {
    uint32_t lo, hi;
    asm("mov.b64 {%0, %1}, %2;" : "=r"(lo), "=r"(hi) : "l"(p));
    return make_float2(__uint_as_float(lo), __uint_as_float(hi));
}

// ---------------- cp.async helpers ------------------------------------------
__device__ __forceinline__ void cp_async16(void* smem, const void* gmem) {
    uint32_t s = (uint32_t)__cvta_generic_to_shared(smem);
    asm volatile("cp.async.cg.shared.global [%0], [%1], 16;\n" :: "r"(s), "l"(gmem));
}
__device__ __forceinline__ void cp_commit() {
    asm volatile("cp.async.commit_group;\n" ::: "memory");
}
template<int N> __device__ __forceinline__ void cp_wait() {
    asm volatile("cp.async.wait_group %0;\n" :: "n"(N) : "memory");
}

// ---------------- K1a: u,v projections (fully coalesced) ---------------------
__global__ void k_prep(const float* __restrict__ W, const float* __restrict__ a) {
    int idx = blockIdx.x * 128 + threadIdx.x;   // 0..1023 = (h,d)
    int h = idx >> 8;
    const float4* wr = (const float4*)(W + (size_t)idx * 128);
    const float4* a1 = (const float4*)(a + h * 256);
    const float4* a2 = (const float4*)(a + h * 256 + 128);
    float av = 0.f, au = 0.f;
    #pragma unroll
    for (int q = 0; q < 32; q++) {
        float4 w = wr[q], x1 = a1[q], x2 = a2[q];
        au += w.x * x1.x + w.y * x1.y + w.z * x1.z + w.w * x1.w;
        av += w.x * x2.x + w.y * x2.y + w.z * x2.z + w.w * x2.w;
    }
    g_v[idx] = av;
    g_u[idx] = au;
}

// ---------------- K1b: score constants c[h] ----------------------------------
__global__ void k_prep2(const float* __restrict__ a, const float* __restrict__ p,
                        const float* __restrict__ bb) {
    int h = threadIdx.x >> 5, lane = threadIdx.x & 31;
    auto warp = cg::tiled_partition<32>(cg::this_thread_block());
    float s = 0.f;
    for (int d = lane; d < 256; d += 32) s += p[d] * g_u[h * 256 + d];
    for (int k = lane; k < 128; k += 32)
        s += bb[h * 128 + k] * (a[h * 256 + k] + a[h * 256 + 128 + k]);
    s = cg::reduce(warp, s, cg::plus<float>());
    if (lane == 0) g_c[h] = s;
}

// ---------------- K2: fused single-pass, warp-autonomous, f32x2 --------------
__global__ void __launch_bounds__(256, 2) k_fused(const float* __restrict__ code) {
    __shared__ float buf[8][DEPTH * 256];          // 64 KB: 8 warps x 8 x 1KB
    __shared__ float cm[8][4], cz[8][4], csc[8][4];

    int t = threadIdx.x, lane = t & 31, w = t >> 5;
    int gw = blockIdx.x * 8 + w;
    int cnt = (N_CODES - gw + NW - 1) / NW;
    auto warp = cg::tiled_partition<32>(cg::this_thread_block());

    float* bw = &buf[w][0];
    const float* base = code + (size_t)gw * 256;

    uint64_t vp[4][4];
    #pragma unroll
    for (int h = 0; h < 4; h++) {
        ulonglong2 va = *(const ulonglong2*)(g_v + h * 256 + lane * 4);
        ulonglong2 vb = *(const ulonglong2*)(g_v + h * 256 + 128 + lane * 4);
        vp[h][0] = va.x; vp[h][1] = va.y; vp[h][2] = vb.x; vp[h][3] = vb.y;
    }
    float c0 = g_c[0], c1 = g_c[1], c2 = g_c[2], c3 = g_c[3];

    float m0 = -1e30f, m1 = -1e30f, m2 = -1e30f, m3 = -1e30f;
    float s0 = 0.f, s1 = 0.f, s2 = 0.f, s3 = 0.f;
    uint64_t acc[4][4];
    #pragma unroll
    for (int h = 0; h < 4; h++)
        #pragma unroll
        for (int k = 0; k < 4; k++) acc[h][k] = 0ull;

    #pragma unroll
    for (int k = 0; k < DEPTH - 1; k++) {
        if (k < cnt) {
            const float* src = base + (size_t)k * NW * 256;
            cp_async16(bw + k * 256 + lane * 4, src + lane * 4);
            cp_async16(bw + k * 256 + 128 + lane * 4, src + 128 + lane * 4);
        }
        cp_commit();
    }

    for (int i = 0; i < cnt; i++) {
        cp_wait<DEPTH - 2>();
        int slot = i % DEPTH;
        ulonglong2 xa = *(const ulonglong2*)(bw + slot * 256 + lane * 4);
        ulonglong2 xb = *(const ulonglong2*)(bw + slot * 256 + 128 + lane * 4);

        int j = i + DEPTH - 1;
        if (j < cnt) {
            const float* src = base + (size_t)j * NW * 256;
            int js = j % DEPTH;
            cp_async16(bw + js * 256 + lane * 4, src + lane * 4);
            cp_async16(bw + js * 256 + 128 + lane * 4, src + 128 + lane * 4);
        }
        cp_commit();

        uint64_t d0 = mul2(vp[0][0], xa.x);
        uint64_t d1 = mul2(vp[1][0], xa.x);
        uint64_t d2 = mul2(vp[2][0], xa.x);
        uint64_t d3 = mul2(vp[3][0], xa.x);
        d0 = fma2(vp[0][1], xa.y, d0); d1 = fma2(vp[1][1], xa.y, d1);
        d2 = fma2(vp[2][1], xa.y, d2); d3 = fma2(vp[3][1], xa.y, d3);
        d0 = fma2(vp[0][2], xb.x, d0); d1 = fma2(vp[1][2], xb.x, d1);
        d2 = fma2(vp[2][2], xb.x, d2); d3 = fma2(vp[3][2], xb.x, d3);
        d0 = fma2(vp[0][3], xb.y, d0); d1 = fma2(vp[1][3], xb.y, d1);
        d2 = fma2(vp[2][3], xb.y, d2); d3 = fma2(vp[3][3], xb.y, d3);
        float2 f0 = unpack2(d0), f1 = unpack2(d1), f2 = unpack2(d2), f3 = unpack2(d3);
        float e0 = f0.x + f0.y, e1 = f1.x + f1.y;
        float e2 = f2.x + f2.y, e3 = f3.x + f3.y;

        e0 = cg::reduce(warp, e0, cg::plus<float>());
        e1 = cg::reduce(warp, e1, cg::plus<float>());
        e2 = cg::reduce(warp, e2, cg::plus<float>());
        e3 = cg::reduce(warp, e3, cg::plus<float>());

        e0 += c0; e1 += c1; e2 += c2; e3 += c3;
        e0 = e0 >= 0.f ? e0 : 0.2f * e0;
        e1 = e1 >= 0.f ? e1 : 0.2f * e1;
        e2 = e2 >= 0.f ? e2 : 0.2f * e2;
        e3 = e3 >= 0.f ? e3 : 0.2f * e3;

        float n0 = fmaxf(m0, e0), n1 = fmaxf(m1, e1);
        float n2 = fmaxf(m2, e2), n3 = fmaxf(m3, e3);
        if (n0 > m0 || n1 > m1 || n2 > m2 || n3 > m3) {
            float r0 = exp2f((m0 - n0) * L2E), r1 = exp2f((m1 - n1) * L2E);
            float r2 = exp2f((m2 - n2) * L2E), r3 = exp2f((m3 - n3) * L2E);
            s0 *= r0; s1 *= r1; s2 *= r2; s3 *= r3;
            uint64_t q0 = pack2(r0), q1 = pack2(r1), q2 = pack2(r2), q3 = pack2(r3);
            #pragma unroll
            for (int k = 0; k < 4; k++) {
                acc[0][k] = mul2(q0, acc[0][k]); acc[1][k] = mul2(q1, acc[1][k]);
                acc[2][k] = mul2(q2, acc[2][k]); acc[3][k] = mul2(q3, acc[3][k]);
            }
            m0 = n0; m1 = n1; m2 = n2; m3 = n3;
        }
        float w0 = exp2f((e0 - m0) * L2E), w1 = exp2f((e1 - m1) * L2E);
        float w2 = exp2f((e2 - m2) * L2E), w3 = exp2f((e3 - m3) * L2E);
        s0 += w0; s1 += w1; s2 += w2; s3 += w3;
        uint64_t p0 = pack2(w0), p1 = pack2(w1), p2 = pack2(w2), p3 = pack2(w3);

        acc[0][0] = fma2(p0, xa.x, acc[0][0]); acc[0][1] = fma2(p0, xa.y, acc[0][1]);
        acc[0][2] = fma2(p0, xb.x, acc[0][2]); acc[0][3] = fma2(p0, xb.y, acc[0][3]);
        acc[1][0] = fma2(p1, xa.x, acc[1][0]); acc[1][1] = fma2(p1, xa.y, acc[1][1]);
        acc[1][2] = fma2(p1, xb.x, acc[1][2]); acc[1][3] = fma2(p1, xb.y, acc[1][3]);
        acc[2][0] = fma2(p2, xa.x, acc[2][0]); acc[2][1] = fma2(p2, xa.y, acc[2][1]);
        acc[2][2] = fma2(p2, xb.x, acc[2][2]); acc[2][3] = fma2(p2, xb.y, acc[2][3]);
        acc[3][0] = fma2(p3, xa.x, acc[3][0]); acc[3][1] = fma2(p3, xa.y, acc[3][1]);
        acc[3][2] = fma2(p3, xb.x, acc[3][2]); acc[3][3] = fma2(p3, xb.y, acc[3][3]);
    }
    cp_wait<0>();

    if (lane == 0) {
        cm[w][0] = m0; cm[w][1] = m1; cm[w][2] = m2; cm[w][3] = m3;
        cz[w][0] = s0; cz[w][1] = s1; cz[w][2] = s2; cz[w][3] = s3;
    }
    __syncthreads();
    if (t < 32) {
        int wp = t >> 2, h = t & 3;
        float mv = cm[wp][h];
        float M = mv;
        M = fmaxf(M, __shfl_xor_sync(0xffffffffu, M, 4));
        M = fmaxf(M, __shfl_xor_sync(0xffffffffu, M, 8));
        M = fmaxf(M, __shfl_xor_sync(0xffffffffu, M, 16));
        float sc = exp2f((mv - M) * L2E);
        csc[wp][h] = sc;
        float z = cz[wp][h] * sc;
        z += __shfl_xor_sync(0xffffffffu, z, 4);
        z += __shfl_xor_sync(0xffffffffu, z, 8);
        z += __shfl_xor_sync(0xffffffffu, z, 16);
        if (t < 4) { g_mb[blockIdx.x * 4 + h] = M; g_zb[blockIdx.x * 4 + h] = z; }
    }
    __syncthreads();
    #pragma unroll
    for (int h = 0; h < 4; h++) {
        float sc = csc[w][h];
        float2 a0 = unpack2(acc[h][0]), a1 = unpack2(acc[h][1]);
        float2 a2 = unpack2(acc[h][2]), a3 = unpack2(acc[h][3]);
        *(float4*)(bw + h * 256 + lane * 4) =
            make_float4(a0.x * sc, a0.y * sc, a1.x * sc, a1.y * sc);
        *(float4*)(bw + h * 256 + 128 + lane * 4) =
            make_float4(a2.x * sc, a2.y * sc, a3.x * sc, a3.y * sc);
    }
    __syncthreads();
    #pragma unroll
    for (int h = 0; h < 4; h++) {
        float v = 0.f;
        #pragma unroll
        for (int w2 = 0; w2 < 8; w2++) v += buf[w2][h * 256 + t];
        g_partB[((size_t)blockIdx.x * 4 + h) * 256 + t] = v;
    }
}

// ---------------- K3a: global M/Z + folded scales ----------------------------
__global__ void k_mz() {
    __shared__ float Msh[4], iZsh[4];
    int t = threadIdx.x, h = t >> 5, lane = t & 31;
    auto warp = cg::tiled_partition<32>(cg::this_thread_block());
    // warp h: reduce over 296 blocks
    float M = -1e30f;
    for (int b = lane; b < GRID; b += 32) M = fmaxf(M, g_mb[b * 4 + h]);
    M = cg::reduce(warp, M, cg::greater<float>());
    float Z = 0.f;
    for (int b = lane; b < GRID; b += 32)
        Z += g_zb[b * 4 + h] * exp2f((g_mb[b * 4 + h] - M) * L2E);
    Z = cg::reduce(warp, Z, cg::plus<float>());
    if (lane == 0) { Msh[h] = M; iZsh[h] = 1.0f / Z; }
    __syncthreads();
    // all 128 threads: folded scales for 1184 (b,h) pairs
    for (int i = t; i < GRID * 4; i += 128) {
        int hh = i & 3;
        g_scale[i] = exp2f((g_mb[i] - Msh[hh]) * L2E) * iZsh[hh];
    }
}

// ---------------- K3b: partial-sum reduction (16 blocks) ---------------------
// block (h, q): sums partB over b in [q*74, (q+1)*74) for all 256 dims
__global__ void k_aggsum() {
    int h = blockIdx.x & 3, q = blockIdx.x >> 2, t = threadIdx.x;
    int b0 = q * 74;
    float acc = 0.f;
    #pragma unroll 4
    for (int b = b0; b < b0 + 74; b++)
        acc = fmaf(g_partB[((size_t)b * 4 + h) * 256 + t], g_scale[b * 4 + h], acc);
    g_part2[(size_t)blockIdx.x * 256 + t] = acc;
}

// ---------------- K3c: final agg + projection --------------------------------
// block h, 1024 threads: agg[d] = sum_q part2; mho[h][k] = agg@W[h][:,k]+b
__global__ void __launch_bounds__(1024) k_aggproj(const float* __restrict__ W,
                                                  const float* __restrict__ bb,
                                                  float* __restrict__ out) {
    int h = blockIdx.x, t = threadIdx.x;
    __shared__ float agg_sh[256];
    __shared__ float red[8][128];
    if (t < 256) {
        float v = 0.f;
        #pragma unroll
        for (int q = 0; q < 4; q++) v += g_part2[((size_t)q * 4 + h) * 256 + t];
        agg_sh[t] = v;
    }
    __syncthreads();
    int k = t & 127, q = t >> 7;             // q in 0..7, 32 d's each
    const float* wp = W + (size_t)h * 256 * 128 + (size_t)q * 32 * 128 + k;
    float acc = 0.f;
    #pragma unroll 8
    for (int d = 0; d < 32; d++)
        acc = fmaf(agg_sh[q * 32 + d], wp[(size_t)d * 128], acc);
    red[q][k] = acc;
    __syncthreads();
    if (t < 128) {
        float v = bb[h * 128 + t];
        #pragma unroll
        for (int qq = 0; qq < 8; qq++) v += red[qq][t];
        g_mho[h * 128 + t] = v;
        out[256 + h * 128 + t] = v;
    }
}

// ---------------- K4: specialty logits (warp per output) ---------------------
__global__ void k_logits(const float* __restrict__ Wc, const float* __restrict__ bc,
                         float* __restrict__ out) {
    int j = blockIdx.x, lane = threadIdx.x;
    auto warp = cg::tiled_partition<32>(cg::this_thread_block());
    const float4* wp = (const float4*)(Wc + (size_t)j * 512);
    const float4* mp = (const float4*)g_mho;
    float acc = 0.f;
    #pragma unroll
    for (int q = 0; q < 4; q++) {
        float4 w = wp[lane + q * 32], m = mp[lane + q * 32];
        acc += w.x * m.x + w.y * m.y + w.z * m.z + w.w * m.w;
    }
    acc = cg::reduce(warp, acc, cg::plus<float>());
    if (lane == 0) out[j] = acc + bc[j];
}

// ---------------- launch ------------------------------------------------------
extern "C" void kernel_launch(void* const* d_in, const int* in_sizes, int n_in,
                              void* d_out, int out_size) {
    const float* p    = (const float*)d_in[0];
    const float* code = (const float*)d_in[1];
    const float* W    = (const float*)d_in[2];
    const float* bb   = (const float*)d_in[3];
    const float* a    = (const float*)d_in[4];
    const float* Wc   = (const float*)d_in[5];
    const float* bc   = (const float*)d_in[6];
    float* out = (float*)d_out;

    k_prep   <<<8,    128>>>(W, a);
    k_prep2  <<<1,    128>>>(a, p, bb);
    k_fused  <<<GRID, 256>>>(code);
    k_mz     <<<1,    128>>>();
    k_aggsum <<<16,   256>>>();
    k_aggproj<<<4,   1024>>>(W, bb, out);
    k_logits <<<256,   32>>>(Wc, bc, out);
}